// round 6
// baseline (speedup 1.0000x reference)
#include <cuda_runtime.h>
#include <cuda_bf16.h>

// B=512, H=8, C=8192.
//   loss = -sum_{b,c} w'[c] * max(lg2(t ? p : 1-p), -100/ln2)
//   w'[c] = (ln2/C) * sum_h lam[h]*La[h,c]
// Single fused kernel: each thread owns one c4 (4 classes) and 4 sample-pairs
// at stride 262144 (multiple of C4). It computes its own w from La (L2-resident)
// in the latency shadow of the 8 DRAM loads. Last-block-done reduction finishes
// the scalar in the same launch.

#define B_DIM 512
#define H_DIM 8
#define C_DIM 8192
#define N4 (B_DIM * C_DIM / 4)        // 1048576 float4 pairs
#define C4 (C_DIM / 4)                // 2048
#define NT 262144                     // total threads
#define NBLOCKS (NT / 256)            // 1024
#define PAIRS 4                       // float4-pairs per thread

#define LOG2_CLAMP (-144.26950408889634f)   // -100 / ln2
#define LN2 (0.6931471805599453f)

__device__ float    g_part[NBLOCKS];
__device__ unsigned g_count;          // zero-init; finisher resets each call

__device__ __forceinline__ float term1(float p, float t) {
    // x = t ? p : 1-p  (exact for binary t)
    float x = fmaf(p, 2.0f * t - 1.0f, 1.0f - t);
    return fmaxf(__log2f(x), LOG2_CLAMP);
}

__global__ void __launch_bounds__(256, 2)
multibce_fused_kernel(const float4* __restrict__ yp,
                      const float4* __restrict__ yt,
                      const float4* __restrict__ La4,   // [H][C4]
                      const float4* __restrict__ lam4,  // [2]
                      float* __restrict__ out) {
    const int tid = blockIdx.x * 256 + threadIdx.x;
    const int c4  = tid & (C4 - 1);

    // ---- main loads (DRAM), issued first ----
    float4 p0 = __ldcs(&yp[tid]);
    float4 p1 = __ldcs(&yp[tid + NT]);
    float4 p2 = __ldcs(&yp[tid + 2 * NT]);
    float4 p3 = __ldcs(&yp[tid + 3 * NT]);
    float4 t0 = __ldcs(&yt[tid]);
    float4 t1 = __ldcs(&yt[tid + NT]);
    float4 t2 = __ldcs(&yt[tid + 2 * NT]);
    float4 t3 = __ldcs(&yt[tid + 3 * NT]);

    // ---- weight computation in the latency shadow (La is L2-resident) ----
    float4 la[H_DIM];
#pragma unroll
    for (int h = 0; h < H_DIM; ++h) la[h] = La4[h * C4 + c4];
    float4 lamA = lam4[0];
    float4 lamB = lam4[1];
    float lamv[H_DIM] = {lamA.x, lamA.y, lamA.z, lamA.w,
                         lamB.x, lamB.y, lamB.z, lamB.w};
    float4 w = make_float4(0.f, 0.f, 0.f, 0.f);
#pragma unroll
    for (int h = 0; h < H_DIM; ++h) {
        w.x = fmaf(lamv[h], la[h].x, w.x);
        w.y = fmaf(lamv[h], la[h].y, w.y);
        w.z = fmaf(lamv[h], la[h].z, w.z);
        w.w = fmaf(lamv[h], la[h].w, w.w);
    }
    const float scale = LN2 / (float)C_DIM;
    w.x *= scale; w.y *= scale; w.z *= scale; w.w *= scale;

    // ---- per-component raw sums (do not wait on w) ----
    float sx = term1(p0.x, t0.x) + term1(p1.x, t1.x)
             + term1(p2.x, t2.x) + term1(p3.x, t3.x);
    float sy = term1(p0.y, t0.y) + term1(p1.y, t1.y)
             + term1(p2.y, t2.y) + term1(p3.y, t3.y);
    float sz = term1(p0.z, t0.z) + term1(p1.z, t1.z)
             + term1(p2.z, t2.z) + term1(p3.z, t3.z);
    float sw = term1(p0.w, t0.w) + term1(p1.w, t1.w)
             + term1(p2.w, t2.w) + term1(p3.w, t3.w);

    float acc = fmaf(w.x, sx, fmaf(w.y, sy, fmaf(w.z, sz, w.w * sw)));

    // ---- warp + block reduce ----
#pragma unroll
    for (int o = 16; o > 0; o >>= 1)
        acc += __shfl_xor_sync(0xFFFFFFFFu, acc, o);

    __shared__ float smem[8];
    __shared__ bool  s_last;
    int lane = threadIdx.x & 31;
    int warp = threadIdx.x >> 5;
    if (lane == 0) smem[warp] = acc;
    __syncthreads();
    if (warp == 0) {
        acc = (lane < 8) ? smem[lane] : 0.0f;
#pragma unroll
        for (int o = 4; o > 0; o >>= 1)
            acc += __shfl_xor_sync(0xFFFFFFFFu, acc, o);
        if (lane == 0) {
            g_part[blockIdx.x] = acc;
            __threadfence();
            unsigned prev = atomicAdd(&g_count, 1u);
            s_last = (prev == (unsigned)(NBLOCKS - 1));
        }
    }
    __syncthreads();

    // ---- finisher block: reduce partials, write scalar, reset counter ----
    if (s_last) {
        float v = g_part[threadIdx.x]
                + g_part[threadIdx.x + 256]
                + g_part[threadIdx.x + 512]
                + g_part[threadIdx.x + 768];
#pragma unroll
        for (int o = 16; o > 0; o >>= 1)
            v += __shfl_xor_sync(0xFFFFFFFFu, v, o);
        if (lane == 0) smem[warp] = v;
        __syncthreads();
        if (warp == 0) {
            v = (lane < 8) ? smem[lane] : 0.0f;
#pragma unroll
            for (int o = 4; o > 0; o >>= 1)
                v += __shfl_xor_sync(0xFFFFFFFFu, v, o);
            if (lane == 0) {
                out[0] = -v;        // loss = -sum
                g_count = 0u;       // reset for next graph replay
            }
        }
    }
}

// ---------------------------------------------------------------------------
extern "C" void kernel_launch(void* const* d_in, const int* in_sizes, int n_in,
                              void* d_out, int out_size) {
    const float* y_pred = (const float*)d_in[0];
    const float* y_true = (const float*)d_in[1];
    const float* La     = (const float*)d_in[2];
    const float* lam    = (const float*)d_in[3];
    float* out = (float*)d_out;

    multibce_fused_kernel<<<NBLOCKS, 256>>>(
        (const float4*)y_pred, (const float4*)y_true,
        (const float4*)La, (const float4*)lam, out);
}

// round 7
// speedup vs baseline: 1.2054x; 1.2054x over previous
#include <cuda_runtime.h>
#include <cuda_bf16.h>

// B=512, H=8, C=8192.
//   loss = -sum_{b,c} w'[c] * max(lg2(t ? p : 1-p), -100/ln2)
//   w'[c] = (ln2/C) * sum_h lam[h]*La[h,c]
// Two kernels (fusion regressed in R6: +32MB L2 traffic).
// Kernel B: depth-1 prefetch pipeline, 4 pairs/thread, stride NT (== 0 mod C4
// so one w vector per thread). Low MLP_p1 avoids cross-CTA L1tex queue pileup.

#define B_DIM 512
#define H_DIM 8
#define C_DIM 8192
#define N4 (B_DIM * C_DIM / 4)        // 1048576 float4 pairs
#define C4 (C_DIM / 4)                // 2048
#define NT 262144                     // total threads in kernel B
#define NBLOCKS (NT / 256)            // 1024
#define PAIRS 4

#define LOG2_CLAMP (-144.26950408889634f)   // -100 / ln2
#define LN2 (0.6931471805599453f)

__device__ float g_w4[C_DIM];         // per-class weight * ln2 / C

// ---------------------------------------------------------------------------
// Kernel A: w'[c] = (ln2/C) * sum_h lam[h]*La[h,c]; zero the output scalar.
// ---------------------------------------------------------------------------
__global__ void multibce_weights_kernel(const float* __restrict__ La,
                                        const float* __restrict__ lam,
                                        float* __restrict__ out) {
    int c = blockIdx.x * blockDim.x + threadIdx.x;
    if (c < C_DIM) {
        float s = 0.0f;
#pragma unroll
        for (int h = 0; h < H_DIM; ++h) {
            s = fmaf(lam[h], La[h * C_DIM + c], s);
        }
        g_w4[c] = s * (LN2 / (float)C_DIM);
    }
    if (c == 0) out[0] = 0.0f;
}

// ---------------------------------------------------------------------------
// Kernel B: weighted BCE reduction with depth-1 load pipeline.
// ---------------------------------------------------------------------------
__device__ __forceinline__ float term1(float p, float t) {
    // x = t ? p : 1-p  (exact for binary t)
    float x = fmaf(p, 2.0f * t - 1.0f, 1.0f - t);
    return fmaxf(__log2f(x), LOG2_CLAMP);
}

__global__ void __launch_bounds__(256, 4)
multibce_reduce_kernel(const float4* __restrict__ yp,
                       const float4* __restrict__ yt,
                       float* __restrict__ out) {
    const int tid = blockIdx.x * 256 + threadIdx.x;

    // Stage 0 loads first (DRAM), then the L2-resident w vector.
    float4 cp = yp[tid];
    float4 ct = yt[tid];
    float4 w  = reinterpret_cast<const float4*>(g_w4)[tid & (C4 - 1)];

    float accx = 0.0f, accy = 0.0f, accz = 0.0f, accw = 0.0f;

#pragma unroll 1
    for (int j = 0; j < PAIRS; ++j) {
        // Prefetch next pair while computing the current one.
        float4 np = cp, nt = ct;
        if (j < PAIRS - 1) {
            np = yp[tid + (j + 1) * NT];
            nt = yt[tid + (j + 1) * NT];
        }
        accx = fmaf(w.x, term1(cp.x, ct.x), accx);
        accy = fmaf(w.y, term1(cp.y, ct.y), accy);
        accz = fmaf(w.z, term1(cp.z, ct.z), accz);
        accw = fmaf(w.w, term1(cp.w, ct.w), accw);
        cp = np; ct = nt;
    }

    float acc = (accx + accy) + (accz + accw);

    // warp reduce
#pragma unroll
    for (int o = 16; o > 0; o >>= 1)
        acc += __shfl_xor_sync(0xFFFFFFFFu, acc, o);

    // block reduce
    __shared__ float smem[8];
    int lane = threadIdx.x & 31;
    int warp = threadIdx.x >> 5;
    if (lane == 0) smem[warp] = acc;
    __syncthreads();
    if (warp == 0) {
        acc = (lane < 8) ? smem[lane] : 0.0f;
#pragma unroll
        for (int o = 4; o > 0; o >>= 1)
            acc += __shfl_xor_sync(0xFFFFFFFFu, acc, o);
        if (lane == 0) atomicAdd(out, -acc);   // loss = -sum
    }
}

// ---------------------------------------------------------------------------
extern "C" void kernel_launch(void* const* d_in, const int* in_sizes, int n_in,
                              void* d_out, int out_size) {
    const float* y_pred = (const float*)d_in[0];
    const float* y_true = (const float*)d_in[1];
    const float* La     = (const float*)d_in[2];
    const float* lam    = (const float*)d_in[3];
    float* out = (float*)d_out;

    multibce_weights_kernel<<<(C_DIM + 255) / 256, 256>>>(La, lam, out);
    multibce_reduce_kernel<<<NBLOCKS, 256>>>(
        (const float4*)y_pred, (const float4*)y_true, out);
}

// round 8
// speedup vs baseline: 1.5283x; 1.2679x over previous
#include <cuda_runtime.h>
#include <cuda_bf16.h>

// B=512, H=8, C=8192.
//   loss = -sum_{b,c} w'[c] * max(lg2(t ? p : 1-p), -100/ln2)
//   w'[c] = (ln2/C) * sum_h lam[h]*La[h,c]
// Two kernels chained with Programmatic Dependent Launch:
//   A triggers B's launch at entry, then computes w into g_w4 and zeroes out.
//   B front-batches its 16 DRAM loads and computes w-free raw sums; only after
//   cudaGridDependencySynchronize() does it read w and finish. A's runtime is
//   hidden inside B's load latency.

#define B_DIM 512
#define H_DIM 8
#define C_DIM 8192
#define N4 (B_DIM * C_DIM / 4)        // 1048576 float4 pairs
#define C4 (C_DIM / 4)                // 2048
#define NT 131072                     // total threads in kernel B
#define NBLOCKS (NT / 256)            // 512 (single wave at 4 blocks/SM)
#define PAIRS 8                       // float4-pairs per thread

#define LOG2_CLAMP (-144.26950408889634f)   // -100 / ln2
#define LN2 (0.6931471805599453f)

__device__ float g_w4[C_DIM];         // per-class weight * ln2 / C

// ---------------------------------------------------------------------------
// Kernel A: trigger B immediately, then compute w and zero the output.
// ---------------------------------------------------------------------------
__global__ void multibce_weights_kernel(const float* __restrict__ La,
                                        const float* __restrict__ lam,
                                        float* __restrict__ out) {
    cudaTriggerProgrammaticLaunchCompletion();
    int c = blockIdx.x * blockDim.x + threadIdx.x;
    if (c < C_DIM) {
        float s = 0.0f;
#pragma unroll
        for (int h = 0; h < H_DIM; ++h) {
            s = fmaf(lam[h], La[h * C_DIM + c], s);
        }
        g_w4[c] = s * (LN2 / (float)C_DIM);
    }
    if (c == 0) out[0] = 0.0f;
}

// ---------------------------------------------------------------------------
// Kernel B: weighted BCE reduction; w-read deferred past gridDepSync.
// ---------------------------------------------------------------------------
__device__ __forceinline__ float term1(float p, float t) {
    // x = t ? p : 1-p  (exact for binary t)
    float x = fmaf(p, 2.0f * t - 1.0f, 1.0f - t);
    return fmaxf(__log2f(x), LOG2_CLAMP);
}

__global__ void __launch_bounds__(256, 4)
multibce_reduce_kernel(const float4* __restrict__ yp,
                       const float4* __restrict__ yt,
                       float* __restrict__ out) {
    const int tid = blockIdx.x * 256 + threadIdx.x;

    float sx = 0.0f, sy = 0.0f, sz = 0.0f, sw = 0.0f;

    // 2 chunks x 4 pairs: 8 LDG.128 batched per chunk (high MLP, R4-proven).
#pragma unroll 1
    for (int j = 0; j < PAIRS / 4; ++j) {
        int base = tid + j * 4 * NT;
        float4 p0 = yp[base];
        float4 p1 = yp[base + NT];
        float4 p2 = yp[base + 2 * NT];
        float4 p3 = yp[base + 3 * NT];
        float4 t0 = yt[base];
        float4 t1 = yt[base + NT];
        float4 t2 = yt[base + 2 * NT];
        float4 t3 = yt[base + 3 * NT];

        sx += term1(p0.x, t0.x) + term1(p1.x, t1.x)
            + term1(p2.x, t2.x) + term1(p3.x, t3.x);
        sy += term1(p0.y, t0.y) + term1(p1.y, t1.y)
            + term1(p2.y, t2.y) + term1(p3.y, t3.y);
        sz += term1(p0.z, t0.z) + term1(p1.z, t1.z)
            + term1(p2.z, t2.z) + term1(p3.z, t3.z);
        sw += term1(p0.w, t0.w) + term1(p1.w, t1.w)
            + term1(p2.w, t2.w) + term1(p3.w, t3.w);
    }

    // Wait for kernel A (w + zeroed out) only now.
    cudaGridDependencySynchronize();
    float4 w = reinterpret_cast<const float4*>(g_w4)[tid & (C4 - 1)];
    float acc = fmaf(w.x, sx, fmaf(w.y, sy, fmaf(w.z, sz, w.w * sw)));

    // warp reduce
#pragma unroll
    for (int o = 16; o > 0; o >>= 1)
        acc += __shfl_xor_sync(0xFFFFFFFFu, acc, o);

    // block reduce
    __shared__ float smem[8];
    int lane = threadIdx.x & 31;
    int warp = threadIdx.x >> 5;
    if (lane == 0) smem[warp] = acc;
    __syncthreads();
    if (warp == 0) {
        acc = (lane < 8) ? smem[lane] : 0.0f;
#pragma unroll
        for (int o = 4; o > 0; o >>= 1)
            acc += __shfl_xor_sync(0xFFFFFFFFu, acc, o);
        if (lane == 0) atomicAdd(out, -acc);   // loss = -sum
    }
}

// ---------------------------------------------------------------------------
extern "C" void kernel_launch(void* const* d_in, const int* in_sizes, int n_in,
                              void* d_out, int out_size) {
    const float* y_pred = (const float*)d_in[0];
    const float* y_true = (const float*)d_in[1];
    const float* La     = (const float*)d_in[2];
    const float* lam    = (const float*)d_in[3];
    float* out = (float*)d_out;

    multibce_weights_kernel<<<(C_DIM + 255) / 256, 256>>>(La, lam, out);

    // Launch B with Programmatic Stream Serialization so it overlaps A.
    cudaLaunchConfig_t cfg = {};
    cfg.gridDim  = dim3(NBLOCKS);
    cfg.blockDim = dim3(256);
    cfg.dynamicSmemBytes = 0;
    cfg.stream = 0;
    cudaLaunchAttribute attr[1];
    attr[0].id = cudaLaunchAttributeProgrammaticStreamSerialization;
    attr[0].val.programmaticStreamSerializationAllowed = 1;
    cfg.attrs = attr;
    cfg.numAttrs = 1;
    cudaLaunchKernelEx(&cfg, multibce_reduce_kernel,
                       (const float4*)y_pred, (const float4*)y_true, out);
}